// round 6
// baseline (speedup 1.0000x reference)
#include <cuda_runtime.h>
#include <math.h>

typedef unsigned long long ull;

#define DTs   0.2f
#define TILEX 52
#define TILEY 54
#define HALOX 6
#define HALOY 5
#define NTX   32
#define NTY   16
#define RPT   4

// ---- packed f32x2 helpers (sm_103a) ----
__device__ __forceinline__ ull fma2(ull a, ull b, ull c) {
    ull d; asm("fma.rn.f32x2 %0, %1, %2, %3;" : "=l"(d) : "l"(a), "l"(b), "l"(c)); return d;
}
__device__ __forceinline__ ull mul2(ull a, ull b) {
    ull d; asm("mul.rn.f32x2 %0, %1, %2;" : "=l"(d) : "l"(a), "l"(b)); return d;
}
__device__ __forceinline__ ull add2(ull a, ull b) {
    ull d; asm("add.rn.f32x2 %0, %1, %2;" : "=l"(d) : "l"(a), "l"(b)); return d;
}
__device__ __forceinline__ ull pk(float lo, float hi) {
    ull r; asm("mov.b64 %0, {%1, %2};" : "=l"(r) : "f"(lo), "f"(hi)); return r;
}
__device__ __forceinline__ float2 up(ull v) {
    float2 t; asm("mov.b64 {%0, %1}, %2;" : "=f"(t.x), "=f"(t.y) : "l"(v)); return t;
}

struct TrueT  { static constexpr bool value = true;  };
struct FalseT { static constexpr bool value = false; };

__global__ __launch_bounds__(NTX * NTY, 2)
void vib6(const float* __restrict__ force,
          const float* __restrict__ cw,
          const float* __restrict__ omega,
          const float* __restrict__ zeta,
          float* __restrict__ out,
          int H, int W, int C)
{
    __shared__ ull xb[2][34][32];   // double-buffered warp-boundary rows (+guards)
    __shared__ ull fs[64][32];      // F*DT pairs

    const int tx = threadIdx.x;
    const int ty = threadIdx.y;
    const int rb = ty * RPT;
    const int plane = blockIdx.z;
    const int c = plane % C;
    const int bx = blockIdx.x, by = blockIdx.y;
    const bool edge = (bx == 0) | (bx == 4) | (by == 0) | (by == 4);

    const int gx0 = bx * TILEX - HALOX;   // even
    const int gy0 = by * TILEY - HALOY;

    // per-channel params
    const float o  = __ldg(omega + c);
    const float zt = __ldg(zeta + c);
    const float w  = log1pf(expf(o));
    const float z  = 1.0f / (1.0f + expf(-zt));
    const float w2 = w * w;
    const float c1s = 1.0f - 2.0f * z * w * DTs;
    const ull c1p   = pk(c1s, c1s);
    const ull cbdtp = pk(-w2 * DTs, -w2 * DTs);
    const ull DTp   = pk(DTs, DTs);

    ull kp[9];
    #pragma unroll
    for (int j = 0; j < 9; j++) {
        const float kv = __ldg(cw + c * 9 + j) * DTs;
        kp[j] = pk(kv, kv);
    }

    const float* fp = force + (size_t)plane * (H * W);
    const int gc0 = gx0 + 2 * tx;          // even -> pair is 8B aligned
    const bool cok = (unsigned)gc0 < (unsigned)W;   // pair all-or-nothing

    ull vv[RPT], xc[RPT], msk[RPT];

    // ---- init: step 1 analytic (v1 = F*DT, x1 = v1*DT) ----
    #pragma unroll
    for (int i = 0; i < RPT; i++) {
        const int gr = gy0 + rb + i;
        float2 f = make_float2(0.0f, 0.0f);
        if (!edge) {
            f = *reinterpret_cast<const float2*>(fp + gr * W + gc0);
        } else {
            const bool ok = cok && ((unsigned)gr < (unsigned)H);
            if (ok) f = *reinterpret_cast<const float2*>(fp + gr * W + gc0);
            const float m = ok ? 1.0f : 0.0f;
            msk[i] = pk(m, m);
        }
        const ull F2 = pk(f.x * DTs, f.y * DTs);
        fs[rb + i][tx] = F2;
        vv[i] = F2;
        xc[i] = mul2(F2, DTp);
    }
    xb[0][2 * ty + 1][tx] = xc[0];
    xb[0][2 * ty + 2][tx] = xc[RPT - 1];
    if (ty == 0) {
        xb[0][0][tx] = 0ULL; xb[0][33][tx] = 0ULL;
        xb[1][0][tx] = 0ULL; xb[1][33][tx] = 0ULL;
    }
    __syncthreads();

    const ull* fsp = &fs[rb][tx];

    // ---- mainloop: 5 fused conv+update steps, 1 barrier each ----
    auto mainloop = [&](auto MASKC) {
        constexpr bool MASK = decltype(MASKC)::value;
        #pragma unroll
        for (int s = 0; s < 5; s++) {
            ull (*curb)[32] = xb[s & 1];
            ull (*nxtb)[32] = xb[(s & 1) ^ 1];

            const ull T = curb[2 * ty][tx];        // row rb-1
            const ull B = curb[2 * ty + 3][tx];    // row rb+RPT
            const float2 t2 = up(T);
            ull Lt = pk(__shfl_up_sync(0xffffffffu, t2.y, 1), t2.x);
            ull Rt = pk(t2.y, __shfl_down_sync(0xffffffffu, t2.x, 1));
            ull Ct = T;
            const float2 m2 = up(xc[0]);
            ull Lm = pk(__shfl_up_sync(0xffffffffu, m2.y, 1), m2.x);
            ull Rm = pk(m2.y, __shfl_down_sync(0xffffffffu, m2.x, 1));

            #pragma unroll
            for (int i = 0; i < RPT; i++) {
                const ull Cb = (i < RPT - 1) ? xc[i + 1] : B;
                const float2 b2 = up(Cb);
                const ull Lb = pk(__shfl_up_sync(0xffffffffu, b2.y, 1), b2.x);
                const ull Rb = pk(b2.y, __shfl_down_sync(0xffffffffu, b2.x, 1));

                ull acc0 = fma2(cbdtp, xc[i], fsp[i * 32]);
                acc0 = fma2(kp[0], Lt, acc0);
                acc0 = fma2(kp[1], Ct, acc0);
                acc0 = fma2(kp[2], Rt, acc0);
                acc0 = fma2(kp[3], Lm, acc0);
                acc0 = fma2(kp[4], xc[i], acc0);
                ull acc1 = mul2(kp[5], Rm);
                acc1 = fma2(kp[6], Lb, acc1);
                acc1 = fma2(kp[7], Cb, acc1);
                acc1 = fma2(kp[8], Rb, acc1);
                acc1 = fma2(c1p, vv[i], acc1);
                vv[i] = add2(acc0, acc1);

                ull xn = fma2(vv[i], DTp, xc[i]);
                if (MASK) xn = mul2(xn, msk[i]);

                Lt = Lm; Ct = xc[i]; Rt = Rm; Lm = Lb; Rm = Rb;
                xc[i] = xn;
            }
            nxtb[2 * ty + 1][tx] = xc[0];
            nxtb[2 * ty + 2][tx] = xc[RPT - 1];
            __syncthreads();
        }
    };

    if (edge) mainloop(TrueT{});
    else      mainloop(FalseT{});

    // ---- packed energy output: cols [6,57] of region = exact tile, STG.64 ----
    float* op = out + (size_t)plane * (H * W);
    const ull hp   = pk(0.5f, 0.5f);
    const ull hw2p = pk(0.5f * w2, 0.5f * w2);
    const bool cstore = (tx >= 3) && (tx <= 28) && cok;   // region cols 6..57
    #pragma unroll
    for (int i = 0; i < RPT; i++) {
        const int r = rb + i;
        if (r < HALOY || r > 58) continue;               // rows 5..58 valid
        const int gr = gy0 + r;
        if (!cstore || (unsigned)gr >= (unsigned)H) continue;
        const ull vv2 = mul2(vv[i], vv[i]);
        const ull xx2 = mul2(xc[i], xc[i]);
        const ull e   = fma2(hw2p, xx2, mul2(hp, vv2));
        *reinterpret_cast<ull*>(op + (size_t)gr * W + gc0) = e;
    }
}

extern "C" void kernel_launch(void* const* d_in, const int* in_sizes, int n_in,
                              void* d_out, int out_size)
{
    const float* force = (const float*)d_in[0];
    const float* cw    = (const float*)d_in[1];
    const float* omega = (const float*)d_in[2];
    const float* zeta  = (const float*)d_in[3];
    float* out = (float*)d_out;

    const int H = 256, W = 256;
    const int C = in_sizes[2];
    const int planes = in_sizes[0] / (H * W);

    dim3 block(NTX, NTY);
    vib6<<<dim3(5, 5, planes), block>>>(force, cw, omega, zeta, out, H, W, C);
}